// round 4
// baseline (speedup 1.0000x reference)
#include <cuda_runtime.h>
#include <cuda_bf16.h>

// out = ((x .* s2) H .* g_tilde) H .* s1  per row, H = Sylvester Hadamard 4096.
//   (W = diag(s1) H diag(g_tilde) H diag(s2); out = x W^T; H symmetric)
// One CTA per row, 256 threads x 16 regs.
// Layout B: i = r*256 + w*32 + l   (reg bits 8-11, lane bits 0-4, warp bits 5-7)
// Layout C: i = w*512 + r*32 + l   (reg bits 5-8,  lane bits 0-4, warp bits 9-11)
// FWHT1: regB{8-11} + shflB{0-4} + [T: B->C] + regC{5-7}
// FWHT2: regC{5-8} + shflC{0-4} + [T: C->B] + regB{9-11}
// Every global and SMEM warp access is 32 consecutive floats: fully coalesced,
// zero bank conflicts, no skew needed.

#define DD 4096
#define NTHREADS 256

__device__ float g_tilde_buf[DD];

__global__ void prep_kernel(const float* __restrict__ g_mu,
                            const float* __restrict__ g_rho,
                            const float* __restrict__ eps) {
    int i = blockIdx.x * blockDim.x + threadIdx.x;
    if (i < DD) {
        float r  = g_rho[i];
        float sp = fmaxf(r, 0.0f) + log1pf(expf(-fabsf(r)));   // stable softplus
        g_tilde_buf[i] = g_mu[i] + sp * eps[i];
    }
}

// Butterfly on in-thread register pairs (element bit = the r-bit selected by MASK).
template <int MASK>
__device__ __forceinline__ void reg_stage(float v[16]) {
#pragma unroll
    for (int r = 0; r < 16; r++) {
        if (!(r & MASK)) {
            float a = v[r], b = v[r | MASK];
            v[r]        = a + b;
            v[r | MASK] = a - b;
        }
    }
}

// Butterfly across lanes: lower lane -> a+b, upper lane -> a-b.
template <int MASK>
__device__ __forceinline__ void shfl_stage(float v[16], int lane) {
    float sgn = (lane & MASK) ? -1.0f : 1.0f;
#pragma unroll
    for (int r = 0; r < 16; r++) {
        float p = __shfl_xor_sync(0xffffffffu, v[r], MASK);
        v[r] = fmaf(sgn, v[r], p);   // p + sgn*own
    }
}

__global__ __launch_bounds__(NTHREADS)
void whvi_kernel(const float* __restrict__ x,
                 const float* __restrict__ s1,
                 const float* __restrict__ s2,
                 float* __restrict__ out) {
    __shared__ float sm[DD];

    const int t = threadIdx.x;
    const int l = t & 31;
    const int w = t >> 5;
    const long row = blockIdx.x;
    const float* __restrict__ xr = x + row * (long)DD;

    float v[16];

    // ---- load row (layout B, coalesced), scale by s2 ----
#pragma unroll
    for (int r = 0; r < 16; r++) {
        int i = r * 256 + w * 32 + l;
        v[r] = __ldcs(xr + i) * __ldg(s2 + i);
    }

    // ---- FWHT #1: bits 8-11 (reg, layout B) ----
    reg_stage<1>(v); reg_stage<2>(v); reg_stage<4>(v); reg_stage<8>(v);
    // ---- FWHT #1: bits 0-4 (lane shuffles) ----
    shfl_stage<1>(v, l); shfl_stage<2>(v, l); shfl_stage<4>(v, l);
    shfl_stage<8>(v, l); shfl_stage<16>(v, l);

    // ---- transpose B -> C (both sides conflict-free) ----
#pragma unroll
    for (int r = 0; r < 16; r++)
        sm[r * 256 + w * 32 + l] = v[r];
    __syncthreads();

    float gt[16];
#pragma unroll
    for (int r = 0; r < 16; r++) {
        v[r]  = sm[w * 512 + r * 32 + l];
        gt[r] = __ldg(&g_tilde_buf[w * 512 + r * 32 + l]);  // prefetch, overlaps stages
    }

    // ---- FWHT #1: bits 5-7 (reg, layout C) -> FWHT #1 complete ----
    reg_stage<1>(v); reg_stage<2>(v); reg_stage<4>(v);

    // ---- elementwise g_tilde (layout C, coalesced) ----
#pragma unroll
    for (int r = 0; r < 16; r++)
        v[r] *= gt[r];

    // ---- FWHT #2: bits 5-8 (reg, layout C) ----
    reg_stage<1>(v); reg_stage<2>(v); reg_stage<4>(v); reg_stage<8>(v);
    // ---- FWHT #2: bits 0-4 (lane shuffles) ----
    shfl_stage<1>(v, l); shfl_stage<2>(v, l); shfl_stage<4>(v, l);
    shfl_stage<8>(v, l); shfl_stage<16>(v, l);

    // ---- transpose C -> B ----
    __syncthreads();   // previous transpose reads complete
#pragma unroll
    for (int r = 0; r < 16; r++)
        sm[w * 512 + r * 32 + l] = v[r];
    __syncthreads();

    float s1f[16];
#pragma unroll
    for (int r = 0; r < 16; r++) {
        v[r]   = sm[r * 256 + w * 32 + l];
        s1f[r] = __ldg(s1 + r * 256 + w * 32 + l);   // prefetch, overlaps stages
    }

    // ---- FWHT #2: bits 9-11 (reg, layout B; bit 8 done in layout C) ----
    reg_stage<2>(v); reg_stage<4>(v); reg_stage<8>(v);

    // ---- scale by s1, store (layout B, coalesced, streaming) ----
    float* __restrict__ outr = out + row * (long)DD;
#pragma unroll
    for (int r = 0; r < 16; r++)
        __stcs(outr + r * 256 + w * 32 + l, v[r] * s1f[r]);
}

extern "C" void kernel_launch(void* const* d_in, const int* in_sizes, int n_in,
                              void* d_out, int out_size) {
    const float* x     = (const float*)d_in[0];
    const float* s1    = (const float*)d_in[1];
    const float* s2    = (const float*)d_in[2];
    const float* g_mu  = (const float*)d_in[3];
    const float* g_rho = (const float*)d_in[4];
    const float* eps   = (const float*)d_in[5];
    float* out = (float*)d_out;

    int B = in_sizes[0] / DD;   // 4096

    prep_kernel<<<DD / NTHREADS, NTHREADS>>>(g_mu, g_rho, eps);
    whvi_kernel<<<B, NTHREADS>>>(x, s1, s2, out);
}